// round 6
// baseline (speedup 1.0000x reference)
#include <cuda_runtime.h>

#define NMAX 4096

static constexpr float R_      = 0.1f;
static constexpr float DT_     = 1.0f / 60.0f;
static constexpr float MAXV    = 3.0f;                 // 0.5*0.1/DT
static constexpr float RHO0    = 17510.1f;
static constexpr float STIFF   = 2.99e-11f;
static constexpr float SPIKY   = 4.774648292756860e6f; // 15/(pi*R^6)
static constexpr float NSPIKY3 = -3.0f * 4.774648292756860e6f;
static constexpr float VDTR    = 60.0f * (1.0f / 60.0f) / 17510.1f; // VISC*DT/RHO0
static constexpr float EPS_    = 1e-8f;
// self-pair contribution to rho: d_self = sqrt(EPS) = 1e-4, t = R - 1e-4
static constexpr float W_SELF  =
    (float)(4.774648292756860e6 * 0.0999 * 0.0999 * 0.0999);

// ---------------- packed f32x2 on b64 registers (no pack/unpack movs) -------
typedef unsigned long long pk;

__device__ __forceinline__ pk pk2(float x, float y) {
    pk r; asm("mov.b64 %0, {%1, %2};" : "=l"(r) : "f"(x), "f"(y)); return r;
}
__device__ __forceinline__ float2 unpk(pk a) {
    float2 f; asm("mov.b64 {%0, %1}, %2;" : "=f"(f.x), "=f"(f.y) : "l"(a));
    return f;
}
__device__ __forceinline__ pk pkadd(pk a, pk b) {
    pk r; asm("add.rn.f32x2 %0, %1, %2;" : "=l"(r) : "l"(a), "l"(b)); return r;
}
__device__ __forceinline__ pk pkmul(pk a, pk b) {
    pk r; asm("mul.rn.f32x2 %0, %1, %2;" : "=l"(r) : "l"(a), "l"(b)); return r;
}
__device__ __forceinline__ pk pkfma(pk a, pk b, pk c) {
    pk r; asm("fma.rn.f32x2 %0, %1, %2, %3;"
              : "=l"(r) : "l"(a), "l"(b), "l"(c)); return r;
}
// packed rsqrt (2x MUFU) and packed max(x,0)
__device__ __forceinline__ pk pkrsq(pk a) {
    float2 f = unpk(a);
    return pk2(rsqrtf(f.x), rsqrtf(f.y));
}
__device__ __forceinline__ pk pkmax0(pk a) {
    float2 f = unpk(a);
    return pk2(fmaxf(f.x, 0.0f), fmaxf(f.y, 0.0f));
}

// ---------------- scratch (device globals: allocation-guard safe) -----------
__device__ __align__(16) float g_ax[NMAX], g_ay[NMAX], g_az[NMAX]; // ping A
__device__ __align__(16) float g_bx[NMAX], g_by[NMAX], g_bz[NMAX]; // ping B
__device__ __align__(16) float g_lam[NMAX];
__device__ __align__(16) float g_vx[NMAX], g_vy[NMAX], g_vz[NMAX];

// ---------------------------------------------------------------------------
// 1) external forces + velocity cap + predicted positions (SoA)
// ---------------------------------------------------------------------------
__global__ void k_predict(const float* __restrict__ locs,
                          const float* __restrict__ vel, int N) {
    int i = blockIdx.x * blockDim.x + threadIdx.x;
    if (i >= N) return;
    float vx = vel[3 * i + 0];
    float vy = vel[3 * i + 1] - 9.8f * DT_;
    float vz = vel[3 * i + 2];
    float nrm = sqrtf(vx * vx + vy * vy + vz * vz);
    float s = fminf(MAXV / (nrm + 1e-4f), 1.0f);
    g_ax[i] = locs[3 * i + 0] + DT_ * vx * s;
    g_ay[i] = locs[3 * i + 1] + DT_ * vy * s;
    g_az[i] = locs[3 * i + 2] + DT_ * vz * s;
}

// shared fill: SoA positions -> smem (float4 vector copies)
__device__ __forceinline__ void fill_pos(float* xs, float* ys, float* zs,
                                         const float* sx, const float* sy,
                                         const float* sz, int N) {
    for (int k = threadIdx.x; k < (N >> 2); k += blockDim.x) {
        ((float4*)xs)[k] = ((const float4*)sx)[k];
        ((float4*)ys)[k] = ((const float4*)sy)[k];
        ((float4*)zs)[k] = ((const float4*)sz)[k];
    }
    __syncthreads();
}

// ---------------------------------------------------------------------------
// 2) lambda pass: rho_i = sum_j w_ij ; lam_i = -(rho-RHO0)*STIFF
//    1 particle / warp, 2 j's / lane (f32x2), positions in SMEM
// ---------------------------------------------------------------------------
__global__ void __launch_bounds__(256, 4) k_lambda(int srcA, int N) {
    __shared__ __align__(16) float xs[NMAX], ys[NMAX], zs[NMAX];
    fill_pos(xs, ys, zs, srcA ? g_ax : g_bx, srcA ? g_ay : g_by,
             srcA ? g_az : g_bz, N);

    int i    = blockIdx.x * (blockDim.x >> 5) + (threadIdx.x >> 5);
    int lane = threadIdx.x & 31;
    if (i >= N) return;

    const pk EPS2 = pk2(EPS_, EPS_), NEG1 = pk2(-1.0f, -1.0f);
    const pk RP = pk2(R_, R_), CP = pk2(SPIKY, SPIKY);
    const pk px = pk2(xs[i], xs[i]);
    const pk py = pk2(ys[i], ys[i]);
    const pk pz = pk2(zs[i], zs[i]);
    pk acc = pk2(0.f, 0.f);

#pragma unroll 4
    for (int j = 2 * lane; j < N; j += 64) {
        pk xj = *(const pk*)&xs[j];
        pk yj = *(const pk*)&ys[j];
        pk zj = *(const pk*)&zs[j];
        pk dx = pkfma(xj, NEG1, px);
        pk dy = pkfma(yj, NEG1, py);
        pk dz = pkfma(zj, NEG1, pz);
        pk d2 = pkfma(dx, dx, EPS2);
        d2 = pkfma(dy, dy, d2);
        d2 = pkfma(dz, dz, d2);
        pk rv = pkrsq(d2);
        pk d  = pkmul(d2, rv);
        pk t  = pkmax0(pkfma(d, NEG1, RP));
        pk t2 = pkmul(t, t);
        pk ct = pkmul(t, CP);
        acc = pkfma(ct, t2, acc);
    }
    float2 a = unpk(acc);
    float s = a.x + a.y;
#pragma unroll
    for (int o = 16; o; o >>= 1) s += __shfl_xor_sync(0xffffffffu, s, o);
    if (lane == 0) g_lam[i] = -((s - W_SELF) - RHO0) * STIFF;
}

// ---------------------------------------------------------------------------
// 3) delta pass: pred_i += sum_j (lam_i+lam_j) * dw_ij / d * (p_i - p_j)
// ---------------------------------------------------------------------------
__global__ void __launch_bounds__(256, 4) k_delta(int srcA, int N) {
    __shared__ __align__(16) float xs[NMAX], ys[NMAX], zs[NMAX];
    fill_pos(xs, ys, zs, srcA ? g_ax : g_bx, srcA ? g_ay : g_by,
             srcA ? g_az : g_bz, N);
    float* dx_o = srcA ? g_bx : g_ax;
    float* dy_o = srcA ? g_by : g_ay;
    float* dz_o = srcA ? g_bz : g_az;

    int i    = blockIdx.x * (blockDim.x >> 5) + (threadIdx.x >> 5);
    int lane = threadIdx.x & 31;
    if (i >= N) return;

    const pk EPS2 = pk2(EPS_, EPS_), NEG1 = pk2(-1.0f, -1.0f);
    const pk RP = pk2(R_, R_), N3P = pk2(NSPIKY3, NSPIKY3);
    const pk px = pk2(xs[i], xs[i]);
    const pk py = pk2(ys[i], ys[i]);
    const pk pz = pk2(zs[i], zs[i]);
    float liv = __ldg(&g_lam[i]);
    const pk li = pk2(liv, liv);
    pk ax = pk2(0.f, 0.f), ay = pk2(0.f, 0.f), az = pk2(0.f, 0.f);

#pragma unroll 4
    for (int j = 2 * lane; j < N; j += 64) {
        pk xj = *(const pk*)&xs[j];
        pk yj = *(const pk*)&ys[j];
        pk zj = *(const pk*)&zs[j];
        pk lj = __ldg((const pk*)&g_lam[j]);
        pk dx = pkfma(xj, NEG1, px);
        pk dy = pkfma(yj, NEG1, py);
        pk dz = pkfma(zj, NEG1, pz);
        pk d2 = pkfma(dx, dx, EPS2);
        d2 = pkfma(dy, dy, d2);
        d2 = pkfma(dz, dz, d2);
        pk rv = pkrsq(d2);
        pk d  = pkmul(d2, rv);
        pk t  = pkmax0(pkfma(d, NEG1, RP));
        pk t2 = pkmul(t, t);
        pk a  = pkmul(t2, N3P);
        pk b  = pkmul(a, rv);
        pk c  = pkmul(pkadd(li, lj), b);
        ax = pkfma(c, dx, ax);
        ay = pkfma(c, dy, ay);
        az = pkfma(c, dz, az);
    }
    float2 fx = unpk(ax), fy = unpk(ay), fz = unpk(az);
    float sx = fx.x + fx.y, sy = fy.x + fy.y, sz = fz.x + fz.y;
#pragma unroll
    for (int o = 16; o; o >>= 1) {
        sx += __shfl_xor_sync(0xffffffffu, sx, o);
        sy += __shfl_xor_sync(0xffffffffu, sy, o);
        sz += __shfl_xor_sync(0xffffffffu, sz, o);
    }
    if (lane == 0) {
        dx_o[i] = xs[i] + sx;
        dy_o[i] = ys[i] + sy;
        dz_o[i] = zs[i] + sz;
    }
}

// ---------------------------------------------------------------------------
// 4) new_vel = (pred - locs)/DT (SoA) ; emit pred to out
//    final pred lives in B after A->B, B->A, A->B
// ---------------------------------------------------------------------------
__global__ void k_nvout(const float* __restrict__ locs,
                        float* __restrict__ out, int N) {
    int i = blockIdx.x * blockDim.x + threadIdx.x;
    if (i >= N) return;
    float px = g_bx[i], py = g_by[i], pz = g_bz[i];
    g_vx[i] = (px - locs[3 * i + 0]) * (1.0f / DT_);
    g_vy[i] = (py - locs[3 * i + 1]) * (1.0f / DT_);
    g_vz[i] = (pz - locs[3 * i + 2]) * (1.0f / DT_);
    out[3 * i + 0] = px;
    out[3 * i + 1] = py;
    out[3 * i + 2] = pz;
}

// ---------------------------------------------------------------------------
// 5) XSPH viscosity: dv_i = sum_j w_ij (v_j - v_i); cap; emit new_vel
// ---------------------------------------------------------------------------
__global__ void __launch_bounds__(256, 4) k_xsph(float* __restrict__ out, int N) {
    __shared__ __align__(16) float xs[NMAX], ys[NMAX], zs[NMAX];
    fill_pos(xs, ys, zs, g_bx, g_by, g_bz, N);

    int i    = blockIdx.x * (blockDim.x >> 5) + (threadIdx.x >> 5);
    int lane = threadIdx.x & 31;
    if (i >= N) return;

    const pk EPS2 = pk2(EPS_, EPS_), NEG1 = pk2(-1.0f, -1.0f);
    const pk RP = pk2(R_, R_), CP = pk2(SPIKY, SPIKY);
    const pk px = pk2(xs[i], xs[i]);
    const pk py = pk2(ys[i], ys[i]);
    const pk pz = pk2(zs[i], zs[i]);
    pk ws = pk2(0.f, 0.f);
    pk wx = pk2(0.f, 0.f), wy = pk2(0.f, 0.f), wz = pk2(0.f, 0.f);

#pragma unroll 4
    for (int j = 2 * lane; j < N; j += 64) {
        pk xj = *(const pk*)&xs[j];
        pk yj = *(const pk*)&ys[j];
        pk zj = *(const pk*)&zs[j];
        pk vx = __ldg((const pk*)&g_vx[j]);
        pk vy = __ldg((const pk*)&g_vy[j]);
        pk vz = __ldg((const pk*)&g_vz[j]);
        pk dx = pkfma(xj, NEG1, px);
        pk dy = pkfma(yj, NEG1, py);
        pk dz = pkfma(zj, NEG1, pz);
        pk d2 = pkfma(dx, dx, EPS2);
        d2 = pkfma(dy, dy, d2);
        d2 = pkfma(dz, dz, d2);
        pk rv = pkrsq(d2);
        pk d  = pkmul(d2, rv);
        pk t  = pkmax0(pkfma(d, NEG1, RP));
        pk wk = pkmul(pkmul(t, CP), pkmul(t, t));
        ws = pkadd(ws, wk);
        wx = pkfma(wk, vx, wx);
        wy = pkfma(wk, vy, wy);
        wz = pkfma(wk, vz, wz);
    }
    float2 fs = unpk(ws), fx = unpk(wx), fy = unpk(wy), fz = unpk(wz);
    float s = fs.x + fs.y;
    float x = fx.x + fx.y, y = fy.x + fy.y, z = fz.x + fz.y;
#pragma unroll
    for (int o = 16; o; o >>= 1) {
        s += __shfl_xor_sync(0xffffffffu, s, o);
        x += __shfl_xor_sync(0xffffffffu, x, o);
        y += __shfl_xor_sync(0xffffffffu, y, o);
        z += __shfl_xor_sync(0xffffffffu, z, o);
    }
    if (lane == 0) {
        float vix = g_vx[i], viy = g_vy[i], viz = g_vz[i];
        float nx = vix + VDTR * (x - s * vix);
        float ny = viy + VDTR * (y - s * viy);
        float nz = viz + VDTR * (z - s * viz);
        float nrm = sqrtf(nx * nx + ny * ny + nz * nz);
        float sc = fminf(MAXV / (nrm + 1e-4f), 1.0f);
        out[3 * N + 3 * i + 0] = nx * sc;
        out[3 * N + 3 * i + 1] = ny * sc;
        out[3 * N + 3 * i + 2] = nz * sc;
    }
}

// ---------------------------------------------------------------------------
extern "C" void kernel_launch(void* const* d_in, const int* in_sizes, int n_in,
                              void* d_out, int out_size) {
    const float* locs = (const float*)d_in[0];
    const float* vel  = (const float*)d_in[1];
    float* out = (float*)d_out;
    int N = in_sizes[0] / 3;  // 4096

    const int TPB = 256;
    int eb = (N + TPB - 1) / TPB;                    // elementwise blocks
    int pb = (N + (TPB / 32) - 1) / (TPB / 32);      // warp-per-particle: 512

    k_predict<<<eb, TPB>>>(locs, vel, N);
    int srcA = 1;
    for (int it = 0; it < 3; ++it) {
        k_lambda<<<pb, TPB>>>(srcA, N);
        k_delta<<<pb, TPB>>>(srcA, N);
        srcA ^= 1;
    }
    k_nvout<<<eb, TPB>>>(locs, out, N);
    k_xsph<<<pb, TPB>>>(out, N);
}